// round 3
// baseline (speedup 1.0000x reference)
#include <cuda_runtime.h>
#include <cuda_bf16.h>

#define HID   128
#define NWARP 8
#define JT    8      // j's per warp tile
#define NTHREADS 256

// shared layout (floats)
#define OFF_W2T   0                       // 128 rows * 132 pitch
#define SZ_W2T    (128*132)
#define OFF_HS    (OFF_W2T + SZ_W2T)      // NWARP*JT*128
#define SZ_HS     (NWARP*JT*128)
#define OFF_FD    (OFF_HS + SZ_HS)        // NWARP*JT*8  (feat float4 + dir float4)
#define SZ_FD     (NWARP*JT*8)
#define OFF_W1    (OFF_FD + SZ_FD)        // 3*128
#define OFF_B1    (OFF_W1 + 384)
#define OFF_B2    (OFF_B1 + 128)
#define OFF_W3    (OFF_B2 + 128)
#define OFF_MAG   (OFF_W3 + 128)          // NWARP*JT
#define OFF_WF    (OFF_MAG + NWARP*JT)    // NWARP*4
#define SMEM_FLOATS (OFF_WF + NWARP*4)
#define SMEM_BYTES  (SMEM_FLOATS * 4)

__device__ __forceinline__ float fast_tanh(float x) {
    x = fminf(fmaxf(x, -15.0f), 15.0f);
    float e = __expf(2.0f * x);
    return 1.0f - __fdividef(2.0f, e + 1.0f);
}

__global__ __launch_bounds__(NTHREADS, 2)
void discoverynet_force_kernel(
    const float* __restrict__ pos,   // (B,N,3)
    const float* __restrict__ W1,    // (3,128)
    const float* __restrict__ b1,    // (128,)
    const float* __restrict__ W2,    // (128,128)  [c][k]
    const float* __restrict__ b2,    // (128,)
    const float* __restrict__ W3,    // (128,1)
    const float* __restrict__ b3,    // (1,)
    float* __restrict__ out,         // (B,N,3)
    int N)
{
    extern __shared__ float sm[];
    float* w2t   = sm + OFF_W2T;   // transposed: w2t[k*132 + c] = W2[c][k]
    float* h_s   = sm + OFF_HS;
    float* fd_s  = sm + OFF_FD;
    float* w1s   = sm + OFF_W1;
    float* b1s   = sm + OFF_B1;
    float* b2s   = sm + OFF_B2;
    float* w3s   = sm + OFF_W3;
    float* mag_s = sm + OFF_MAG;
    float* wf_s  = sm + OFF_WF;

    const int tid  = threadIdx.x;
    const int w    = tid >> 5;
    const int lane = tid & 31;
    const int i    = blockIdx.x;
    const int b    = blockIdx.y;

    // ---- load weights into shared ----
    for (int idx = tid; idx < 128 * 128; idx += NTHREADS) {
        int c = idx >> 7;
        int k = idx & 127;
        w2t[k * 132 + c] = W2[idx];
    }
    for (int idx = tid; idx < 384; idx += NTHREADS)   // FIX: 384 > NTHREADS, must stride
        w1s[idx] = W1[idx];
    if (tid < 128) {
        b1s[tid] = b1[tid];
        b2s[tid] = b2[tid];
        w3s[tid] = W3[tid];
    }
    const float b3v = b3[0];
    __syncthreads();

    const float* pos_b = pos + (size_t)b * N * 3;
    const float xi = pos_b[i * 3 + 0];
    const float yi = pos_b[i * 3 + 1];
    const float zi = pos_b[i * 3 + 2];

    float fx = 0.0f, fy = 0.0f, fz = 0.0f;

    const int ntiles = N / (NWARP * JT);   // 16
    for (int jt = 0; jt < ntiles; ++jt) {
        const int jbase = jt * (NWARP * JT) + w * JT;

        // ---- phase A: features + directions (lanes 0..7, one j each) ----
        if (lane < JT) {
            const int j = jbase + lane;
            float dx = xi - pos_b[j * 3 + 0];
            float dy = yi - pos_b[j * 3 + 1];
            float dz = zi - pos_b[j * 3 + 2];
            float dist = sqrtf(dx * dx + dy * dy + dz * dz);
            float dc   = fmaxf(dist, 0.01f);
            float inv  = 1.0f / dc;
            float4* fd = (float4*)(fd_s + (w * JT + lane) * 8);
            fd[0] = make_float4(dist, inv, inv * inv, 0.0f);
            fd[1] = make_float4(dx * inv, dy * inv, dz * inv, 0.0f);
        }
        __syncwarp();

        // ---- layer 1: 3 -> 128, tanh ----
        #pragma unroll
        for (int jl = 0; jl < JT; ++jl) {
            float4 f = *(const float4*)(fd_s + (w * JT + jl) * 8);
            #pragma unroll
            for (int u = 0; u < 4; ++u) {
                int k = lane + 32 * u;
                float pre = fmaf(f.x, w1s[k],
                            fmaf(f.y, w1s[128 + k],
                            fmaf(f.z, w1s[256 + k], b1s[k])));
                h_s[(w * JT + jl) * 128 + k] = fast_tanh(pre);
            }
        }
        __syncwarp();

        // ---- layer 2: 128 -> 128 (register-blocked GEMM, 8j x 4k per lane) ----
        float acc[JT][4];
        #pragma unroll
        for (int jl = 0; jl < JT; ++jl)
            #pragma unroll
            for (int u = 0; u < 4; ++u) acc[jl][u] = 0.0f;

        #pragma unroll 4
        for (int c = 0; c < 128; c += 4) {
            float4 wv[4];
            #pragma unroll
            for (int u = 0; u < 4; ++u)
                wv[u] = *(const float4*)(w2t + (lane + 32 * u) * 132 + c);
            #pragma unroll
            for (int jl = 0; jl < JT; ++jl) {
                float4 hv = *(const float4*)(h_s + (w * JT + jl) * 128 + c);
                #pragma unroll
                for (int u = 0; u < 4; ++u) {
                    acc[jl][u] = fmaf(hv.x, wv[u].x, acc[jl][u]);
                    acc[jl][u] = fmaf(hv.y, wv[u].y, acc[jl][u]);
                    acc[jl][u] = fmaf(hv.z, wv[u].z, acc[jl][u]);
                    acc[jl][u] = fmaf(hv.w, wv[u].w, acc[jl][u]);
                }
            }
        }

        // ---- layer 3: tanh, dot with W3, warp-reduce per j ----
        float m[JT];
        #pragma unroll
        for (int jl = 0; jl < JT; ++jl) {
            float s = 0.0f;
            #pragma unroll
            for (int u = 0; u < 4; ++u) {
                int k = lane + 32 * u;
                float h2 = fast_tanh(acc[jl][u] + b2s[k]);
                s = fmaf(h2, w3s[k], s);
            }
            m[jl] = s;
        }
        #pragma unroll
        for (int jl = 0; jl < JT; ++jl) {
            #pragma unroll
            for (int off = 16; off > 0; off >>= 1)
                m[jl] += __shfl_xor_sync(0xffffffffu, m[jl], off);
        }
        if (lane == 0) {
            #pragma unroll
            for (int jl = 0; jl < JT; ++jl)
                mag_s[w * JT + jl] = m[jl] + b3v;
        }
        __syncwarp();

        // ---- force accumulation (lanes 0..7, one j each; j==i gives dir=0) ----
        if (lane < JT) {
            float mg  = mag_s[w * JT + lane];
            float4 d4 = *(const float4*)(fd_s + (w * JT + lane) * 8 + 4);
            fx = fmaf(mg, d4.x, fx);
            fy = fmaf(mg, d4.y, fy);
            fz = fmaf(mg, d4.z, fz);
        }
        __syncwarp();   // protect fd_s/h_s before next tile overwrites
    }

    // ---- reduce forces across lanes 0..7 of each warp ----
    #pragma unroll
    for (int off = 4; off > 0; off >>= 1) {
        fx += __shfl_xor_sync(0xffffffffu, fx, off);
        fy += __shfl_xor_sync(0xffffffffu, fy, off);
        fz += __shfl_xor_sync(0xffffffffu, fz, off);
    }
    if (lane == 0) {
        wf_s[w * 4 + 0] = fx;
        wf_s[w * 4 + 1] = fy;
        wf_s[w * 4 + 2] = fz;
    }
    __syncthreads();

    if (tid < 3) {
        float s = 0.0f;
        #pragma unroll
        for (int ww = 0; ww < NWARP; ++ww) s += wf_s[ww * 4 + tid];
        out[((size_t)b * N + i) * 3 + tid] = s;
    }
}

extern "C" void kernel_launch(void* const* d_in, const int* in_sizes, int n_in,
                              void* d_out, int out_size) {
    const float* pos = (const float*)d_in[0];
    const float* W1  = (const float*)d_in[1];
    const float* b1  = (const float*)d_in[2];
    const float* W2  = (const float*)d_in[3];
    const float* b2  = (const float*)d_in[4];
    const float* W3  = (const float*)d_in[5];
    const float* b3  = (const float*)d_in[6];
    float* out = (float*)d_out;

    const int N = 1024;
    const int B = in_sizes[0] / (N * 3);

    cudaFuncSetAttribute(discoverynet_force_kernel,
                         cudaFuncAttributeMaxDynamicSharedMemorySize, SMEM_BYTES);

    dim3 grid(N, B);
    discoverynet_force_kernel<<<grid, NTHREADS, SMEM_BYTES>>>(
        pos, W1, b1, W2, b2, W3, b3, out, N);
}

// round 5
// speedup vs baseline: 51.6530x; 51.6530x over previous
#include <cuda_runtime.h>
#include <cuda_bf16.h>

// ===================== table parameters =====================
#define TN      32768                 // table entries
#define T_LO    (-24.0f)              // t = log2(d^2); d in [2^-12, 32]
#define T_HI    (10.0f)
#define HT      ((T_HI - T_LO) / (float)TN)
#define INV_HT  ((float)TN / (T_HI - T_LO))

__device__ float  g_Hval[TN + 4];     // H at grid g = m-2, m in [0, TN+3]
__device__ float4 g_tab4[TN];         // g_tab4[k] = H at grid {k-1, k, k+1, k+2}

// ===================== setup kernel (R3 body on grid entries) =====================
#define NWARP 8
#define JT    8
#define NTHREADS 256

#define OFF_W2T   0
#define SZ_W2T    (128*132)
#define OFF_HS    (OFF_W2T + SZ_W2T)
#define SZ_HS     (NWARP*JT*128)
#define OFF_FD    (OFF_HS + SZ_HS)
#define SZ_FD     (NWARP*JT*8)
#define OFF_W1    (OFF_FD + SZ_FD)
#define OFF_B1    (OFF_W1 + 384)
#define OFF_B2    (OFF_B1 + 128)
#define OFF_W3    (OFF_B2 + 128)
#define OFF_MAG   (OFF_W3 + 128)
#define SMEM_FLOATS (OFF_MAG + NWARP*JT)
#define SMEM_BYTES  (SMEM_FLOATS * 4)

__device__ __forceinline__ float fast_tanh(float x) {
    x = fminf(fmaxf(x, -15.0f), 15.0f);
    float e = __expf(2.0f * x);
    return 1.0f - __fdividef(2.0f, e + 1.0f);
}

__global__ __launch_bounds__(NTHREADS, 2)
void build_table_kernel(
    const float* __restrict__ W1, const float* __restrict__ b1,
    const float* __restrict__ W2, const float* __restrict__ b2,
    const float* __restrict__ W3, const float* __restrict__ b3)
{
    extern __shared__ float sm[];
    float* w2t   = sm + OFF_W2T;   // w2t[k*132 + c] = W2[c][k]
    float* h_s   = sm + OFF_HS;
    float* fd_s  = sm + OFF_FD;
    float* w1s   = sm + OFF_W1;
    float* b1s   = sm + OFF_B1;
    float* b2s   = sm + OFF_B2;
    float* w3s   = sm + OFF_W3;
    float* mag_s = sm + OFF_MAG;

    const int tid  = threadIdx.x;
    const int w    = tid >> 5;
    const int lane = tid & 31;

    for (int idx = tid; idx < 128 * 128; idx += NTHREADS) {
        int c = idx >> 7;
        int k = idx & 127;
        w2t[k * 132 + c] = W2[idx];
    }
    for (int idx = tid; idx < 384; idx += NTHREADS) w1s[idx] = W1[idx];
    if (tid < 128) {
        b1s[tid] = b1[tid];
        b2s[tid] = b2[tid];
        w3s[tid] = W3[tid];
    }
    const float b3v = b3[0];
    __syncthreads();

    const int ebase = blockIdx.x * (NWARP * JT) + w * JT;

    // ---- features for this warp's 8 grid entries ----
    if (lane < JT) {
        int e = ebase + lane;
        float t = T_LO + (float)(e - 2) * HT;     // grid g = e-2
        float d = exp2f(0.5f * t);
        float dc  = fmaxf(d, 0.01f);
        float inv = 1.0f / dc;
        float4* fd = (float4*)(fd_s + (w * JT + lane) * 8);
        fd[0] = make_float4(d, inv, inv * inv, 0.0f);
        fd[1] = make_float4(inv, 0.0f, 0.0f, 0.0f);   // stash inv
    }
    __syncwarp();

    // ---- layer 1 ----
    #pragma unroll
    for (int jl = 0; jl < JT; ++jl) {
        float4 f = *(const float4*)(fd_s + (w * JT + jl) * 8);
        #pragma unroll
        for (int u = 0; u < 4; ++u) {
            int k = lane + 32 * u;
            float pre = fmaf(f.x, w1s[k],
                        fmaf(f.y, w1s[128 + k],
                        fmaf(f.z, w1s[256 + k], b1s[k])));
            h_s[(w * JT + jl) * 128 + k] = fast_tanh(pre);
        }
    }
    __syncwarp();

    // ---- layer 2 ----
    float acc[JT][4];
    #pragma unroll
    for (int jl = 0; jl < JT; ++jl)
        #pragma unroll
        for (int u = 0; u < 4; ++u) acc[jl][u] = 0.0f;

    #pragma unroll 4
    for (int c = 0; c < 128; c += 4) {
        float4 wv[4];
        #pragma unroll
        for (int u = 0; u < 4; ++u)
            wv[u] = *(const float4*)(w2t + (lane + 32 * u) * 132 + c);
        #pragma unroll
        for (int jl = 0; jl < JT; ++jl) {
            float4 hv = *(const float4*)(h_s + (w * JT + jl) * 128 + c);
            #pragma unroll
            for (int u = 0; u < 4; ++u) {
                acc[jl][u] = fmaf(hv.x, wv[u].x, acc[jl][u]);
                acc[jl][u] = fmaf(hv.y, wv[u].y, acc[jl][u]);
                acc[jl][u] = fmaf(hv.z, wv[u].z, acc[jl][u]);
                acc[jl][u] = fmaf(hv.w, wv[u].w, acc[jl][u]);
            }
        }
    }

    // ---- layer 3 ----
    float m[JT];
    #pragma unroll
    for (int jl = 0; jl < JT; ++jl) {
        float s = 0.0f;
        #pragma unroll
        for (int u = 0; u < 4; ++u) {
            int k = lane + 32 * u;
            float h2 = fast_tanh(acc[jl][u] + b2s[k]);
            s = fmaf(h2, w3s[k], s);
        }
        m[jl] = s;
    }
    #pragma unroll
    for (int jl = 0; jl < JT; ++jl) {
        #pragma unroll
        for (int off = 16; off > 0; off >>= 1)
            m[jl] += __shfl_xor_sync(0xffffffffu, m[jl], off);
    }
    if (lane == 0) {
        #pragma unroll
        for (int jl = 0; jl < JT; ++jl)
            mag_s[w * JT + jl] = m[jl] + b3v;
    }
    __syncwarp();

    // ---- write H = mag * inv ----
    if (lane < JT) {
        int e = ebase + lane;
        if (e < TN + 4) {
            float inv = fd_s[(w * JT + lane) * 8 + 4];
            g_Hval[e] = mag_s[w * JT + lane] * inv;
        }
    }
}

// ===================== pack kernel =====================
__global__ void pack_table_kernel() {
    int k = blockIdx.x * blockDim.x + threadIdx.x;
    if (k < TN)
        g_tab4[k] = make_float4(g_Hval[k + 1], g_Hval[k + 2],
                                g_Hval[k + 3], g_Hval[k + 4]);
}

// ===================== force kernel =====================
__global__ __launch_bounds__(256)
void force_kernel(const float* __restrict__ pos, float* __restrict__ out, int N)
{
    __shared__ float4 pos4[1024];
    const int tid = threadIdx.x;
    const int b   = blockIdx.y;
    const float* pos_b = pos + (size_t)b * N * 3;

    for (int idx = tid; idx < N; idx += 256)
        pos4[idx] = make_float4(pos_b[idx * 3 + 0], pos_b[idx * 3 + 1],
                                pos_b[idx * 3 + 2], 0.0f);
    __syncthreads();

    const int w    = tid >> 5;
    const int lane = tid & 31;
    const int i    = blockIdx.x * 8 + w;     // one i per warp
    const float4 pi = pos4[i];

    float fx = 0.0f, fy = 0.0f, fz = 0.0f;

    #pragma unroll 8
    for (int jj = 0; jj < 32; ++jj) {
        int j = jj * 32 + lane;
        float4 pj = pos4[j];
        float dx = pi.x - pj.x;
        float dy = pi.y - pj.y;
        float dz = pi.z - pj.z;
        float s = fmaf(dx, dx, fmaf(dy, dy, dz * dz));
        float t = __log2f(s);                         // s=0 -> -inf -> clamps
        float u = (t - T_LO) * INV_HT;
        u = fminf(fmaxf(u, 0.0f), (float)TN - 1.001f);
        int   k = (int)u;
        float f = u - (float)k;
        float4 hv = __ldg(&g_tab4[k]);                // H at grid k-1..k+2
        // Catmull-Rom
        float c = hv.y + 0.5f * f * ((hv.z - hv.x) +
                  f * ((2.0f * hv.x - 5.0f * hv.y + 4.0f * hv.z - hv.w) +
                  f * (3.0f * (hv.y - hv.z) + (hv.w - hv.x))));
        fx = fmaf(c, dx, fx);
        fy = fmaf(c, dy, fy);
        fz = fmaf(c, dz, fz);
    }

    #pragma unroll
    for (int off = 16; off > 0; off >>= 1) {
        fx += __shfl_xor_sync(0xffffffffu, fx, off);
        fy += __shfl_xor_sync(0xffffffffu, fy, off);
        fz += __shfl_xor_sync(0xffffffffu, fz, off);
    }
    if (lane == 0) {
        float* o = out + ((size_t)b * N + i) * 3;
        o[0] = fx; o[1] = fy; o[2] = fz;
    }
}

// ===================== launch =====================
extern "C" void kernel_launch(void* const* d_in, const int* in_sizes, int n_in,
                              void* d_out, int out_size) {
    const float* pos = (const float*)d_in[0];
    const float* W1  = (const float*)d_in[1];
    const float* b1  = (const float*)d_in[2];
    const float* W2  = (const float*)d_in[3];
    const float* b2  = (const float*)d_in[4];
    const float* W3  = (const float*)d_in[5];
    const float* b3  = (const float*)d_in[6];
    float* out = (float*)d_out;

    const int N = 1024;
    const int B = in_sizes[0] / (N * 3);

    cudaFuncSetAttribute(build_table_kernel,
                         cudaFuncAttributeMaxDynamicSharedMemorySize, SMEM_BYTES);

    const int nblk = (TN + 4 + NWARP * JT - 1) / (NWARP * JT);   // 513
    build_table_kernel<<<nblk, NTHREADS, SMEM_BYTES>>>(W1, b1, W2, b2, W3, b3);
    pack_table_kernel<<<TN / 256, 256>>>();
    force_kernel<<<dim3(N / 8, B), 256>>>(pos, out, N);
}

// round 9
// speedup vs baseline: 96.5318x; 1.8689x over previous
#include <cuda_runtime.h>
#include <cuda_bf16.h>

// ===================== table parameters =====================
#define TN      8192                  // table entries
#define T_LO    (-24.0f)              // t = log2(d^2); d in [2^-12, 32]
#define T_HI    (10.0f)
#define HT      ((T_HI - T_LO) / (float)TN)
#define INV_HT  ((float)TN / (T_HI - T_LO))

__device__ float  g_Hval[TN + 4];     // H at grid g = m-2, m in [0, TN+3]
__device__ float4 g_tab4[TN];         // g_tab4[k] = H at grid {k-1, k, k+1, k+2}

// ===================== setup kernel =====================
#define NWARP 8
#define JT    4                       // entries per warp (32/block -> 257 blocks)
#define NTHREADS 256

#define OFF_W2T   0
#define SZ_W2T    (128*132)
#define OFF_HS    (OFF_W2T + SZ_W2T)
#define SZ_HS     (NWARP*JT*128)
#define OFF_FD    (OFF_HS + SZ_HS)
#define SZ_FD     (NWARP*JT*8)
#define OFF_W1    (OFF_FD + SZ_FD)
#define OFF_B1    (OFF_W1 + 384)
#define OFF_B2    (OFF_B1 + 128)
#define OFF_W3    (OFF_B2 + 128)
#define OFF_MAG   (OFF_W3 + 128)
#define SMEM_FLOATS (OFF_MAG + NWARP*JT)
#define SMEM_BYTES  (SMEM_FLOATS * 4)

__device__ __forceinline__ float fast_tanh(float x) {
    x = fminf(fmaxf(x, -15.0f), 15.0f);
    float e = __expf(2.0f * x);
    return 1.0f - __fdividef(2.0f, e + 1.0f);
}

__global__ __launch_bounds__(NTHREADS, 2)
void build_table_kernel(
    const float* __restrict__ W1, const float* __restrict__ b1,
    const float* __restrict__ W2, const float* __restrict__ b2,
    const float* __restrict__ W3, const float* __restrict__ b3)
{
    extern __shared__ float sm[];
    float* w2t   = sm + OFF_W2T;   // w2t[k*132 + c] = W2[c][k]
    float* h_s   = sm + OFF_HS;
    float* fd_s  = sm + OFF_FD;
    float* w1s   = sm + OFF_W1;
    float* b1s   = sm + OFF_B1;
    float* b2s   = sm + OFF_B2;
    float* w3s   = sm + OFF_W3;
    float* mag_s = sm + OFF_MAG;

    const int tid  = threadIdx.x;
    const int w    = tid >> 5;
    const int lane = tid & 31;

    for (int idx = tid; idx < 128 * 128; idx += NTHREADS) {
        int c = idx >> 7;
        int k = idx & 127;
        w2t[k * 132 + c] = W2[idx];
    }
    for (int idx = tid; idx < 384; idx += NTHREADS) w1s[idx] = W1[idx];
    if (tid < 128) {
        b1s[tid] = b1[tid];
        b2s[tid] = b2[tid];
        w3s[tid] = W3[tid];
    }
    const float b3v = b3[0];
    __syncthreads();

    const int ebase = blockIdx.x * (NWARP * JT) + w * JT;

    // ---- features for this warp's JT grid entries ----
    if (lane < JT) {
        int e = ebase + lane;
        float t = T_LO + (float)(e - 2) * HT;     // grid g = e-2
        float d = exp2f(0.5f * t);
        float dc  = fmaxf(d, 0.01f);
        float inv = 1.0f / dc;
        float4* fd = (float4*)(fd_s + (w * JT + lane) * 8);
        fd[0] = make_float4(d, inv, inv * inv, 0.0f);
        fd[1] = make_float4(inv, 0.0f, 0.0f, 0.0f);   // stash inv
    }
    __syncwarp();

    // ---- layer 1 ----
    #pragma unroll
    for (int jl = 0; jl < JT; ++jl) {
        float4 f = *(const float4*)(fd_s + (w * JT + jl) * 8);
        #pragma unroll
        for (int u = 0; u < 4; ++u) {
            int k = lane + 32 * u;
            float pre = fmaf(f.x, w1s[k],
                        fmaf(f.y, w1s[128 + k],
                        fmaf(f.z, w1s[256 + k], b1s[k])));
            h_s[(w * JT + jl) * 128 + k] = fast_tanh(pre);
        }
    }
    __syncwarp();

    // ---- layer 2 ----
    float acc[JT][4];
    #pragma unroll
    for (int jl = 0; jl < JT; ++jl)
        #pragma unroll
        for (int u = 0; u < 4; ++u) acc[jl][u] = 0.0f;

    #pragma unroll 4
    for (int c = 0; c < 128; c += 4) {
        float4 wv[4];
        #pragma unroll
        for (int u = 0; u < 4; ++u)
            wv[u] = *(const float4*)(w2t + (lane + 32 * u) * 132 + c);
        #pragma unroll
        for (int jl = 0; jl < JT; ++jl) {
            float4 hv = *(const float4*)(h_s + (w * JT + jl) * 128 + c);
            #pragma unroll
            for (int u = 0; u < 4; ++u) {
                acc[jl][u] = fmaf(hv.x, wv[u].x, acc[jl][u]);
                acc[jl][u] = fmaf(hv.y, wv[u].y, acc[jl][u]);
                acc[jl][u] = fmaf(hv.z, wv[u].z, acc[jl][u]);
                acc[jl][u] = fmaf(hv.w, wv[u].w, acc[jl][u]);
            }
        }
    }

    // ---- layer 3 ----
    float m[JT];
    #pragma unroll
    for (int jl = 0; jl < JT; ++jl) {
        float s = 0.0f;
        #pragma unroll
        for (int u = 0; u < 4; ++u) {
            int k = lane + 32 * u;
            float h2 = fast_tanh(acc[jl][u] + b2s[k]);
            s = fmaf(h2, w3s[k], s);
        }
        m[jl] = s;
    }
    #pragma unroll
    for (int jl = 0; jl < JT; ++jl) {
        #pragma unroll
        for (int off = 16; off > 0; off >>= 1)
            m[jl] += __shfl_xor_sync(0xffffffffu, m[jl], off);
    }
    if (lane == 0) {
        #pragma unroll
        for (int jl = 0; jl < JT; ++jl)
            mag_s[w * JT + jl] = m[jl] + b3v;
    }
    __syncwarp();

    // ---- write H = mag * inv ----
    if (lane < JT) {
        int e = ebase + lane;
        if (e < TN + 4) {
            float inv = fd_s[(w * JT + lane) * 8 + 4];
            g_Hval[e] = mag_s[w * JT + lane] * inv;
        }
    }
}

// ===================== pack kernel =====================
__global__ void pack_table_kernel() {
    int k = blockIdx.x * blockDim.x + threadIdx.x;
    if (k < TN)
        g_tab4[k] = make_float4(g_Hval[k + 1], g_Hval[k + 2],
                                g_Hval[k + 3], g_Hval[k + 4]);
}

// ===================== force kernel =====================
__global__ __launch_bounds__(256)
void force_kernel(const float* __restrict__ pos, float* __restrict__ out, int N)
{
    __shared__ float4 pos4[1024];
    const int tid = threadIdx.x;
    const int b   = blockIdx.y;
    const float* pos_b = pos + (size_t)b * N * 3;

    for (int idx = tid; idx < N; idx += 256)
        pos4[idx] = make_float4(pos_b[idx * 3 + 0], pos_b[idx * 3 + 1],
                                pos_b[idx * 3 + 2], 0.0f);
    __syncthreads();

    const int w    = tid >> 5;
    const int lane = tid & 31;
    const int i    = blockIdx.x * 8 + w;     // one i per warp
    const float4 pi = pos4[i];

    float fx = 0.0f, fy = 0.0f, fz = 0.0f;

    #pragma unroll 8
    for (int jj = 0; jj < 32; ++jj) {
        int j = jj * 32 + lane;
        float4 pj = pos4[j];
        float dx = pi.x - pj.x;
        float dy = pi.y - pj.y;
        float dz = pi.z - pj.z;
        float s = fmaf(dx, dx, fmaf(dy, dy, dz * dz));
        float t = __log2f(s);                         // s=0 -> -inf -> clamps
        float u = (t - T_LO) * INV_HT;
        u = fminf(fmaxf(u, 0.0f), (float)TN - 1.001f);
        int   k = (int)u;
        float f = u - (float)k;
        float4 hv = __ldg(&g_tab4[k]);                // H at grid k-1..k+2
        // Catmull-Rom
        float c = hv.y + 0.5f * f * ((hv.z - hv.x) +
                  f * ((2.0f * hv.x - 5.0f * hv.y + 4.0f * hv.z - hv.w) +
                  f * (3.0f * (hv.y - hv.z) + (hv.w - hv.x))));
        fx = fmaf(c, dx, fx);
        fy = fmaf(c, dy, fy);
        fz = fmaf(c, dz, fz);
    }

    #pragma unroll
    for (int off = 16; off > 0; off >>= 1) {
        fx += __shfl_xor_sync(0xffffffffu, fx, off);
        fy += __shfl_xor_sync(0xffffffffu, fy, off);
        fz += __shfl_xor_sync(0xffffffffu, fz, off);
    }
    if (lane == 0) {
        float* o = out + ((size_t)b * N + i) * 3;
        o[0] = fx; o[1] = fy; o[2] = fz;
    }
}

// ===================== launch =====================
extern "C" void kernel_launch(void* const* d_in, const int* in_sizes, int n_in,
                              void* d_out, int out_size) {
    const float* pos = (const float*)d_in[0];
    const float* W1  = (const float*)d_in[1];
    const float* b1  = (const float*)d_in[2];
    const float* W2  = (const float*)d_in[3];
    const float* b2  = (const float*)d_in[4];
    const float* W3  = (const float*)d_in[5];
    const float* b3  = (const float*)d_in[6];
    float* out = (float*)d_out;

    const int N = 1024;
    const int B = in_sizes[0] / (N * 3);

    cudaFuncSetAttribute(build_table_kernel,
                         cudaFuncAttributeMaxDynamicSharedMemorySize, SMEM_BYTES);

    const int nblk = (TN + 4 + NWARP * JT - 1) / (NWARP * JT);   // 257
    build_table_kernel<<<nblk, NTHREADS, SMEM_BYTES>>>(W1, b1, W2, b2, W3, b3);
    pack_table_kernel<<<TN / 256, 256>>>();
    force_kernel<<<dim3(N / 8, B), 256>>>(pos, out, N);
}

// round 10
// speedup vs baseline: 120.1722x; 1.2449x over previous
#include <cuda_runtime.h>
#include <cuda_bf16.h>

// ===================== table parameters =====================
#define TN      4096                  // table entries
#define T_LO    (-24.0f)              // t = log2(d^2); d in [2^-12, 32]
#define T_HI    (10.0f)
#define HT      ((T_HI - T_LO) / (float)TN)
#define INV_HT  ((float)TN / (T_HI - T_LO))

__device__ float  g_Hval[TN + 4];     // H at grid g = m-2, m in [0, TN+3]
__device__ float4 g_tab4[TN];         // g_tab4[k] = H at grid {k-1, k, k+1, k+2}

// ===================== build kernel (no W2 staging) =====================
#define BNWARP 8
#define BJT    4                      // entries per warp
#define BNTHREADS 256
#define ENTRIES_PER_BLOCK (BNWARP * BJT)   // 32

__device__ __forceinline__ float fast_tanh(float x) {
    x = fminf(fmaxf(x, -15.0f), 15.0f);
    float e = __expf(2.0f * x);
    return 1.0f - __fdividef(2.0f, e + 1.0f);
}

__global__ __launch_bounds__(BNTHREADS)
void build_table_kernel(
    const float* __restrict__ W1, const float* __restrict__ b1,
    const float* __restrict__ W2, const float* __restrict__ b2,
    const float* __restrict__ W3, const float* __restrict__ b3)
{
    __shared__ float h_s[BNWARP * BJT * 128];   // 16KB

    const int tid  = threadIdx.x;
    const int w    = tid >> 5;
    const int lane = tid & 31;

    // lane owns k = 4*lane + u, u in 0..3
    const float4 w1r0 = ((const float4*)W1)[lane];          // row 0
    const float4 w1r1 = ((const float4*)(W1 + 128))[lane];  // row 1
    const float4 w1r2 = ((const float4*)(W1 + 256))[lane];  // row 2
    const float4 b1v  = ((const float4*)b1)[lane];
    const float4 b2v  = ((const float4*)b2)[lane];
    const float4 w3v  = ((const float4*)W3)[lane];
    const float  b3v  = b3[0];

    const int ebase = blockIdx.x * ENTRIES_PER_BLOCK + w * BJT;

    // ---- features + layer 1 (every lane computes its 4 k's for each entry) ----
    float invs[BJT];
    #pragma unroll
    for (int jl = 0; jl < BJT; ++jl) {
        int e = ebase + jl;
        float t  = T_LO + (float)(e - 2) * HT;    // grid g = e-2
        float d  = exp2f(0.5f * t);
        float dc = fmaxf(d, 0.01f);
        float inv = 1.0f / dc;
        invs[jl] = inv;
        float inv2 = inv * inv;

        float4 pre;
        pre.x = fmaf(d, w1r0.x, fmaf(inv, w1r1.x, fmaf(inv2, w1r2.x, b1v.x)));
        pre.y = fmaf(d, w1r0.y, fmaf(inv, w1r1.y, fmaf(inv2, w1r2.y, b1v.y)));
        pre.z = fmaf(d, w1r0.z, fmaf(inv, w1r1.z, fmaf(inv2, w1r2.z, b1v.z)));
        pre.w = fmaf(d, w1r0.w, fmaf(inv, w1r1.w, fmaf(inv2, w1r2.w, b1v.w)));

        float4 h;
        h.x = fast_tanh(pre.x);
        h.y = fast_tanh(pre.y);
        h.z = fast_tanh(pre.z);
        h.w = fast_tanh(pre.w);
        ((float4*)(h_s + (w * BJT + jl) * 128))[lane] = h;
    }
    __syncwarp();

    // ---- layer 2: acc[jl][u] = sum_c h[jl][c] * W2[c][4*lane+u] ----
    float4 acc[BJT];
    #pragma unroll
    for (int jl = 0; jl < BJT; ++jl) acc[jl] = make_float4(0.f, 0.f, 0.f, 0.f);

    #pragma unroll 8
    for (int c4 = 0; c4 < 32; ++c4) {
        float4 wv0 = ((const float4*)(W2 + (c4 * 4 + 0) * 128))[lane];
        float4 wv1 = ((const float4*)(W2 + (c4 * 4 + 1) * 128))[lane];
        float4 wv2 = ((const float4*)(W2 + (c4 * 4 + 2) * 128))[lane];
        float4 wv3 = ((const float4*)(W2 + (c4 * 4 + 3) * 128))[lane];
        #pragma unroll
        for (int jl = 0; jl < BJT; ++jl) {
            float4 hv = ((const float4*)(h_s + (w * BJT + jl) * 128))[c4];  // broadcast
            acc[jl].x = fmaf(hv.x, wv0.x, acc[jl].x);
            acc[jl].y = fmaf(hv.x, wv0.y, acc[jl].y);
            acc[jl].z = fmaf(hv.x, wv0.z, acc[jl].z);
            acc[jl].w = fmaf(hv.x, wv0.w, acc[jl].w);
            acc[jl].x = fmaf(hv.y, wv1.x, acc[jl].x);
            acc[jl].y = fmaf(hv.y, wv1.y, acc[jl].y);
            acc[jl].z = fmaf(hv.y, wv1.z, acc[jl].z);
            acc[jl].w = fmaf(hv.y, wv1.w, acc[jl].w);
            acc[jl].x = fmaf(hv.z, wv2.x, acc[jl].x);
            acc[jl].y = fmaf(hv.z, wv2.y, acc[jl].y);
            acc[jl].z = fmaf(hv.z, wv2.z, acc[jl].z);
            acc[jl].w = fmaf(hv.z, wv2.w, acc[jl].w);
            acc[jl].x = fmaf(hv.w, wv3.x, acc[jl].x);
            acc[jl].y = fmaf(hv.w, wv3.y, acc[jl].y);
            acc[jl].z = fmaf(hv.w, wv3.z, acc[jl].z);
            acc[jl].w = fmaf(hv.w, wv3.w, acc[jl].w);
        }
    }

    // ---- layer 3 + reduce + write ----
    #pragma unroll
    for (int jl = 0; jl < BJT; ++jl) {
        float s;
        {
            float h2x = fast_tanh(acc[jl].x + b2v.x);
            float h2y = fast_tanh(acc[jl].y + b2v.y);
            float h2z = fast_tanh(acc[jl].z + b2v.z);
            float h2w = fast_tanh(acc[jl].w + b2v.w);
            s = fmaf(h2x, w3v.x, fmaf(h2y, w3v.y, fmaf(h2z, w3v.z, h2w * w3v.w)));
        }
        #pragma unroll
        for (int off = 16; off > 0; off >>= 1)
            s += __shfl_xor_sync(0xffffffffu, s, off);
        if (lane == 0) {
            int e = ebase + jl;
            if (e < TN + 4)
                g_Hval[e] = (s + b3v) * invs[jl];
        }
    }
}

// ===================== pack kernel =====================
__global__ void pack_table_kernel() {
    int k = blockIdx.x * blockDim.x + threadIdx.x;
    if (k < TN)
        g_tab4[k] = make_float4(g_Hval[k + 1], g_Hval[k + 2],
                                g_Hval[k + 3], g_Hval[k + 4]);
}

// ===================== force kernel =====================
__global__ __launch_bounds__(256)
void force_kernel(const float* __restrict__ pos, float* __restrict__ out, int N)
{
    __shared__ float4 pos4[1024];
    const int tid = threadIdx.x;
    const int b   = blockIdx.y;
    const float* pos_b = pos + (size_t)b * N * 3;

    for (int idx = tid; idx < N; idx += 256)
        pos4[idx] = make_float4(pos_b[idx * 3 + 0], pos_b[idx * 3 + 1],
                                pos_b[idx * 3 + 2], 0.0f);
    __syncthreads();

    const int w    = tid >> 5;
    const int lane = tid & 31;
    const int i    = blockIdx.x * 8 + w;     // one i per warp
    const float4 pi = pos4[i];

    float fx = 0.0f, fy = 0.0f, fz = 0.0f;

    #pragma unroll 8
    for (int jj = 0; jj < 32; ++jj) {
        int j = jj * 32 + lane;
        float4 pj = pos4[j];
        float dx = pi.x - pj.x;
        float dy = pi.y - pj.y;
        float dz = pi.z - pj.z;
        float s = fmaf(dx, dx, fmaf(dy, dy, dz * dz));
        float t = __log2f(s);                         // s=0 -> -inf -> clamps
        float u = (t - T_LO) * INV_HT;
        u = fminf(fmaxf(u, 0.0f), (float)TN - 1.001f);
        int   k = (int)u;
        float f = u - (float)k;
        float4 hv = __ldg(&g_tab4[k]);                // H at grid k-1..k+2
        // Catmull-Rom
        float c = hv.y + 0.5f * f * ((hv.z - hv.x) +
                  f * ((2.0f * hv.x - 5.0f * hv.y + 4.0f * hv.z - hv.w) +
                  f * (3.0f * (hv.y - hv.z) + (hv.w - hv.x))));
        fx = fmaf(c, dx, fx);
        fy = fmaf(c, dy, fy);
        fz = fmaf(c, dz, fz);
    }

    #pragma unroll
    for (int off = 16; off > 0; off >>= 1) {
        fx += __shfl_xor_sync(0xffffffffu, fx, off);
        fy += __shfl_xor_sync(0xffffffffu, fy, off);
        fz += __shfl_xor_sync(0xffffffffu, fz, off);
    }
    if (lane == 0) {
        float* o = out + ((size_t)b * N + i) * 3;
        o[0] = fx; o[1] = fy; o[2] = fz;
    }
}

// ===================== launch =====================
extern "C" void kernel_launch(void* const* d_in, const int* in_sizes, int n_in,
                              void* d_out, int out_size) {
    const float* pos = (const float*)d_in[0];
    const float* W1  = (const float*)d_in[1];
    const float* b1  = (const float*)d_in[2];
    const float* W2  = (const float*)d_in[3];
    const float* b2  = (const float*)d_in[4];
    const float* W3  = (const float*)d_in[5];
    const float* b3  = (const float*)d_in[6];
    float* out = (float*)d_out;

    const int N = 1024;
    const int B = in_sizes[0] / (N * 3);

    const int nblk = (TN + 4 + ENTRIES_PER_BLOCK - 1) / ENTRIES_PER_BLOCK;  // 129
    build_table_kernel<<<nblk, BNTHREADS>>>(W1, b1, W2, b2, W3, b3);
    pack_table_kernel<<<TN / 256, 256>>>();
    force_kernel<<<dim3(N / 8, B), 256>>>(pos, out, N);
}